// round 4
// baseline (speedup 1.0000x reference)
#include <cuda_runtime.h>
#include <math.h>

// Problem constants
#define BB 4
#define SS 256
#define NN 512
#define RR 32
#define LL (NN * RR)          // 16384 output samples per batch
#define NCHUNK 8
#define S_PER_CHUNK (SS / NCHUNK)  // 32
#define NE 513                // extended segments: head(1) + 511 mids + tail entry
#define NQ 129                // ceil(513/4) segment-quads per batch

// Reference-matching constants
#define TWO_PI_D 6.283185307179586
#define CF_F  ((float)(TWO_PI_D / 44100.0))
#define CMOD_F ((float)TWO_PI_D)
#define INV_CMOD_F ((float)(1.0 / (double)((float)TWO_PI_D)))

// Scratch
__device__ float4 d_tab[BB * SS * NE];       // {base_mod, g, dg/64, a}
__device__ float  d_da [BB * SS * NE];       // a_{i+1}-a_i

// ---------------------------------------------------------------------------
// double-float helpers (all-fp32 compensated arithmetic)
// ---------------------------------------------------------------------------
__device__ __forceinline__ float2 two_sum(float a, float b) {
    float s  = a + b;
    float bb = s - a;
    float e  = (a - (s - bb)) + (b - bb);
    return make_float2(s, e);
}
__device__ __forceinline__ float2 df_add(float2 a, float2 b) {
    float2 s = two_sum(a.x, b.x);
    float lo = s.y + (a.y + b.y);
    float hi = s.x + lo;
    lo = lo - (hi - s.x);
    return make_float2(hi, lo);
}

// ---------------------------------------------------------------------------
// Kernel 1: df-precision prefix of omegas -> per-segment fp32 table.
// ---------------------------------------------------------------------------
__global__ void k_base(const float* __restrict__ freq,
                       const float* __restrict__ amp) {
    int seq  = blockIdx.x;
    int i    = threadIdx.x;
    int lane = i & 31;
    int wid  = i >> 5;

    float f = freq[seq * NN + i];
    float a = amp [seq * NN + i];

    float g_hi = f * CF_F;
    float g_lo = fmaf(f, CF_F, -g_hi);      // exact product tail
    float2 x = make_float2(g_hi, g_lo);

    #pragma unroll
    for (int off = 1; off < 32; off <<= 1) {
        float yh = __shfl_up_sync(0xFFFFFFFFu, x.x, off);
        float yl = __shfl_up_sync(0xFFFFFFFFu, x.y, off);
        if (lane >= off) x = df_add(x, make_float2(yh, yl));
    }

    __shared__ float2 wsum[16];
    if (lane == 31) wsum[wid] = x;
    __syncthreads();
    if (wid == 0) {
        float2 y = (lane < 16) ? wsum[lane] : make_float2(0.0f, 0.0f);
        #pragma unroll
        for (int off = 1; off < 16; off <<= 1) {
            float zh = __shfl_up_sync(0xFFFFFFFFu, y.x, off);
            float zl = __shfl_up_sync(0xFFFFFFFFu, y.y, off);
            if (lane >= off) y = df_add(y, make_float2(zh, zl));
        }
        if (lane < 16) wsum[lane] = y;
    }
    __syncthreads();
    float2 Q = x;
    if (wid > 0) Q = df_add(Q, wsum[wid - 1]);

    float2 Q32  = make_float2(32.0f * Q.x, 32.0f * Q.y);
    float2 g16n = make_float2(-16.0f * g_hi, -16.0f * g_lo);
    float2 P = df_add(Q32, g16n);

    float q = floorf(P.x * INV_CMOD_F);
    float m = fmaf(-q, CMOD_F, P.x) + P.y;

    float fnext = (i < NN - 1) ? freq[seq * NN + i + 1] : f;
    float anext = (i < NN - 1) ? amp [seq * NN + i + 1] : a;
    float dg64 = (i < NN - 1) ? (fnext * CF_F - g_hi) * (1.0f / 64.0f) : 0.0f;
    float da   = (i < NN - 1) ? (anext - a) : 0.0f;

    size_t tb = (size_t)seq * NE;
    d_tab[tb + i + 1] = make_float4(m, g_hi, dg64, a);
    d_da [tb + i + 1] = da;
    if (i == 0) {
        d_tab[tb] = make_float4(0.0f, g_hi, 0.0f, a);
        d_da [tb] = 0.0f;
    }
}

// ---------------------------------------------------------------------------
// Kernel 2: synthesis, 4 t-samples per thread sharing each table load.
// Block = 256 thr = 8 sine-chunks (warps) x [4 segments x 8 lanes].
// Warp lanes span segments e..e+3 -> table loads hit 64B contiguous.
// Fixed-order smem reduction over chunks => deterministic.
// ---------------------------------------------------------------------------
__global__ void k_main(float* __restrict__ out) {
    int tid  = threadIdx.x;
    int c    = tid >> 5;            // sine chunk 0..7
    int lane = tid & 31;
    int seg4 = lane >> 3;           // local segment 0..3
    int jg   = lane & 7;            // j-group: samples j = jg + 8m

    int q = blockIdx.x % NQ;        // segment quad
    int b = blockIdx.x / NQ;
    int e = 4 * q + seg4;           // extended segment index (may exceed 512)
    int ec = (e > NE - 1) ? (NE - 1) : e;   // clamp for safe loads

    // per-sample constants: u_m = j+1, w_m = (2j+1)/64, j = jg + 8m
    float u0 = (float)(jg + 1),  u1 = u0 + 8.0f, u2_ = u0 + 16.0f, u3 = u0 + 24.0f;
    float s0 = u0 * u0, s1 = u1 * u1, s2 = u2_ * u2_, s3 = u3 * u3;
    float w0 = (float)(2 * jg + 1) * (1.0f / 64.0f);
    float w1 = w0 + 0.25f, w2 = w0 + 0.5f, w3 = w0 + 0.75f;

    size_t rowbase = (size_t)(b * SS + c * S_PER_CHUNK) * NE + ec;
    const float4* tp = d_tab + rowbase;
    const float*  dp = d_da  + rowbase;

    float a0 = 0.0f, a1 = 0.0f, a2 = 0.0f, a3 = 0.0f;
    #pragma unroll 8
    for (int k = 0; k < S_PER_CHUNK; k++) {
        float4 v  = __ldg(tp);
        float  da = __ldg(dp);

        float p0 = fmaf(s0, v.z, fmaf(u0, v.y, v.x));
        float p1 = fmaf(s1, v.z, fmaf(u1, v.y, v.x));
        float p2 = fmaf(s2, v.z, fmaf(u2_, v.y, v.x));
        float p3 = fmaf(s3, v.z, fmaf(u3, v.y, v.x));

        float q0 = floorf(p0 * INV_CMOD_F);
        float q1 = floorf(p1 * INV_CMOD_F);
        float q2 = floorf(p2 * INV_CMOD_F);
        float q3 = floorf(p3 * INV_CMOD_F);

        float r0 = fmaf(q0, -CMOD_F, p0);
        float r1 = fmaf(q1, -CMOD_F, p1);
        float r2 = fmaf(q2, -CMOD_F, p2);
        float r3 = fmaf(q3, -CMOD_F, p3);

        float m0 = fmaf(w0, da, v.w);
        float m1 = fmaf(w1, da, v.w);
        float m2 = fmaf(w2, da, v.w);
        float m3 = fmaf(w3, da, v.w);

        a0 = fmaf(m0, __sinf(r0), a0);
        a1 = fmaf(m1, __sinf(r1), a1);
        a2 = fmaf(m2, __sinf(r2), a2);
        a3 = fmaf(m3, __sinf(r3), a3);

        tp += NE; dp += NE;
    }

    // smem: [chunk][segment-local sample], padded rows (33) to dodge conflicts
    __shared__ float sred[NCHUNK][4 * 33];
    int base = seg4 * 33 + jg;
    sred[c][base     ] = a0;
    sred[c][base +  8] = a1;
    sred[c][base + 16] = a2;
    sred[c][base + 24] = a3;
    __syncthreads();

    if (tid < 128) {
        int e_loc = tid >> 5;
        int j     = tid & 31;
        int e_out = 4 * q + e_loc;
        float s = 0.0f;
        #pragma unroll
        for (int cc = 0; cc < NCHUNK; cc++) s += sred[cc][e_loc * 33 + j];

        bool valid = (e_out <= NE - 1);
        if (e_out == 0 || e_out == NE - 1) valid = valid && (j < 16);
        if (valid) {
            int t = (e_out == 0) ? j : 16 + 32 * (e_out - 1) + j;
            out[b * LL + t] = s;
        }
    }
}

// ---------------------------------------------------------------------------
extern "C" void kernel_launch(void* const* d_in, const int* in_sizes, int n_in,
                              void* d_out, int out_size) {
    const float* freq = (const float*)d_in[0];
    const float* amp  = (const float*)d_in[1];
    float* out = (float*)d_out;

    k_base<<<BB * SS, NN>>>(freq, amp);        // 1024 blocks x 512
    k_main<<<BB * NQ, 256>>>(out);             // 516 blocks x 256
}

// round 5
// speedup vs baseline: 1.0137x; 1.0137x over previous
#include <cuda_runtime.h>
#include <math.h>

// Problem constants
#define BB 4
#define SS 256
#define NN 512
#define RR 32
#define LL (NN * RR)          // 16384 output samples per batch
#define NCHUNK 8
#define S_PER_CHUNK (SS / NCHUNK)  // 32
#define NE 513                // extended segments: head(1) + 511 mids + tail
#define NQ2 257               // ceil(513/2) segment-pairs per batch

// Reference-matching constants
#define TWO_PI_D 6.283185307179586
#define CF_F  ((float)(TWO_PI_D / 44100.0))
#define CMOD_F ((float)TWO_PI_D)
#define INV_CMOD_F ((float)(1.0 / (double)((float)TWO_PI_D)))

// Scratch
__device__ float4 d_tab[BB * SS * NE];       // {base_mod, g, dg/64, a}
__device__ float  d_da [BB * SS * NE];       // a_{i+1}-a_i

// ---------------------------------------------------------------------------
// double-float helpers (all-fp32 compensated arithmetic)
// ---------------------------------------------------------------------------
__device__ __forceinline__ float2 two_sum(float a, float b) {
    float s  = a + b;
    float bb = s - a;
    float e  = (a - (s - bb)) + (b - bb);
    return make_float2(s, e);
}
__device__ __forceinline__ float2 df_add(float2 a, float2 b) {
    float2 s = two_sum(a.x, b.x);
    float lo = s.y + (a.y + b.y);
    float hi = s.x + lo;
    lo = lo - (hi - s.x);
    return make_float2(hi, lo);
}

// ---------------------------------------------------------------------------
// Kernel 1: df-precision prefix of omegas -> per-segment fp32 table.
// ---------------------------------------------------------------------------
__global__ void k_base(const float* __restrict__ freq,
                       const float* __restrict__ amp) {
    int seq  = blockIdx.x;
    int i    = threadIdx.x;
    int lane = i & 31;
    int wid  = i >> 5;

    float f = freq[seq * NN + i];
    float a = amp [seq * NN + i];

    float g_hi = f * CF_F;
    float g_lo = fmaf(f, CF_F, -g_hi);      // exact product tail
    float2 x = make_float2(g_hi, g_lo);

    #pragma unroll
    for (int off = 1; off < 32; off <<= 1) {
        float yh = __shfl_up_sync(0xFFFFFFFFu, x.x, off);
        float yl = __shfl_up_sync(0xFFFFFFFFu, x.y, off);
        if (lane >= off) x = df_add(x, make_float2(yh, yl));
    }

    __shared__ float2 wsum[16];
    if (lane == 31) wsum[wid] = x;
    __syncthreads();
    if (wid == 0) {
        float2 y = (lane < 16) ? wsum[lane] : make_float2(0.0f, 0.0f);
        #pragma unroll
        for (int off = 1; off < 16; off <<= 1) {
            float zh = __shfl_up_sync(0xFFFFFFFFu, y.x, off);
            float zl = __shfl_up_sync(0xFFFFFFFFu, y.y, off);
            if (lane >= off) y = df_add(y, make_float2(zh, zl));
        }
        if (lane < 16) wsum[lane] = y;
    }
    __syncthreads();
    float2 Q = x;
    if (wid > 0) Q = df_add(Q, wsum[wid - 1]);

    float2 Q32  = make_float2(32.0f * Q.x, 32.0f * Q.y);
    float2 g16n = make_float2(-16.0f * g_hi, -16.0f * g_lo);
    float2 P = df_add(Q32, g16n);

    float q = floorf(P.x * INV_CMOD_F);
    float m = fmaf(-q, CMOD_F, P.x) + P.y;

    float fnext = (i < NN - 1) ? freq[seq * NN + i + 1] : f;
    float anext = (i < NN - 1) ? amp [seq * NN + i + 1] : a;
    float dg64 = (i < NN - 1) ? (fnext * CF_F - g_hi) * (1.0f / 64.0f) : 0.0f;
    float da   = (i < NN - 1) ? (anext - a) : 0.0f;

    size_t tb = (size_t)seq * NE;
    d_tab[tb + i + 1] = make_float4(m, g_hi, dg64, a);
    d_da [tb + i + 1] = da;
    if (i == 0) {
        d_tab[tb] = make_float4(0.0f, g_hi, 0.0f, a);
        d_da [tb] = 0.0f;
    }
}

// ---------------------------------------------------------------------------
// Kernel 2: synthesis. Block = 256 thr = 8 sine-chunks (warps) x
// [2 segments x 16 lanes]; each thread computes 2 t-samples of one segment
// (j = jg, jg+16), sharing each table load across both. Grid = B * 257
// segment-pairs -> ~7 blocks/SM for latency hiding.
// Fixed-order smem reduction over chunks => bitwise deterministic.
// ---------------------------------------------------------------------------
__global__ void __launch_bounds__(256) k_main(float* __restrict__ out) {
    int tid  = threadIdx.x;
    int c    = tid >> 5;            // sine chunk 0..7
    int lane = tid & 31;
    int seg2 = lane >> 4;           // local segment 0..1
    int jg   = lane & 15;           // j-group: samples j = jg, jg+16

    int q = blockIdx.x % NQ2;       // segment pair
    int b = blockIdx.x / NQ2;
    int e = 2 * q + seg2;           // extended segment index (may be 513)
    int ec = (e > NE - 1) ? (NE - 1) : e;   // clamp for safe loads

    float u0 = (float)(jg + 1);
    float u1 = u0 + 16.0f;
    float s0 = u0 * u0, s1 = u1 * u1;
    float w0 = (float)(2 * jg + 1) * (1.0f / 64.0f);
    float w1 = w0 + 0.5f;

    size_t rowbase = (size_t)(b * SS + c * S_PER_CHUNK) * NE + ec;
    const float4* tp = d_tab + rowbase;
    const float*  dp = d_da  + rowbase;

    float a0 = 0.0f, a1 = 0.0f;
    #pragma unroll 8
    for (int k = 0; k < S_PER_CHUNK; k++) {
        float4 v  = __ldg(tp);
        float  da = __ldg(dp);

        float p0 = fmaf(s0, v.z, fmaf(u0, v.y, v.x));
        float p1 = fmaf(s1, v.z, fmaf(u1, v.y, v.x));

        float q0 = floorf(p0 * INV_CMOD_F);
        float q1 = floorf(p1 * INV_CMOD_F);

        float r0 = fmaf(q0, -CMOD_F, p0);
        float r1 = fmaf(q1, -CMOD_F, p1);

        float m0 = fmaf(w0, da, v.w);
        float m1 = fmaf(w1, da, v.w);

        a0 = fmaf(m0, __sinf(r0), a0);
        a1 = fmaf(m1, __sinf(r1), a1);

        tp += NE; dp += NE;
    }

    // smem: [chunk][segment-local sample], padded rows (33) vs conflicts
    __shared__ float sred[NCHUNK][2 * 33];
    int base = seg2 * 33 + jg;
    sred[c][base     ] = a0;
    sred[c][base + 16] = a1;
    __syncthreads();

    if (tid < 64) {
        int e_loc = tid >> 5;           // 0..1
        int j     = tid & 31;
        int e_out = 2 * q + e_loc;
        float s = 0.0f;
        #pragma unroll
        for (int cc = 0; cc < NCHUNK; cc++) s += sred[cc][e_loc * 33 + j];

        bool valid = (e_out <= NE - 1);
        if (e_out == 0 || e_out == NE - 1) valid = valid && (j < 16);
        if (valid) {
            int t = (e_out == 0) ? j : 16 + 32 * (e_out - 1) + j;
            out[b * LL + t] = s;
        }
    }
}

// ---------------------------------------------------------------------------
extern "C" void kernel_launch(void* const* d_in, const int* in_sizes, int n_in,
                              void* d_out, int out_size) {
    const float* freq = (const float*)d_in[0];
    const float* amp  = (const float*)d_in[1];
    float* out = (float*)d_out;

    k_base<<<BB * SS, NN>>>(freq, amp);        // 1024 blocks x 512
    k_main<<<BB * NQ2, 256>>>(out);            // 1028 blocks x 256
}

// round 6
// speedup vs baseline: 1.1235x; 1.1083x over previous
#include <cuda_runtime.h>
#include <math.h>

// Problem constants
#define BB 4
#define SS 256
#define NN 512
#define RR 32
#define LL (NN * RR)          // 16384 output samples per batch
#define NCHUNK 8
#define S_PER_CHUNK (SS / NCHUNK)  // 32
#define NE 513                // extended segments: head(1) + 511 mids + tail
#define NQ2 257               // ceil(513/2) segment-pairs per batch

// Reference-matching constants
#define TWO_PI_D 6.283185307179586
#define CF_F  ((float)(TWO_PI_D / 44100.0))
#define CMOD_F ((float)TWO_PI_D)
#define INV_CMOD_F ((float)(1.0 / (double)((float)TWO_PI_D)))
#define MAGIC_F 12582912.0f   // 1.5 * 2^23: fma(x, s, MAGIC)-MAGIC = round-to-nearest(x*s)

// Scratch (+NE padding so the software-pipeline prefetch may over-read 1 row)
__device__ float4 d_tab[BB * SS * NE + NE];  // {base_mod, g, dg/64, a}
__device__ float  d_da [BB * SS * NE + NE];  // a_{i+1}-a_i

// ---------------------------------------------------------------------------
// double-float helpers (all-fp32 compensated arithmetic)
// ---------------------------------------------------------------------------
__device__ __forceinline__ float2 two_sum(float a, float b) {
    float s  = a + b;
    float bb = s - a;
    float e  = (a - (s - bb)) + (b - bb);
    return make_float2(s, e);
}
__device__ __forceinline__ float2 df_add(float2 a, float2 b) {
    float2 s = two_sum(a.x, b.x);
    float lo = s.y + (a.y + b.y);
    float hi = s.x + lo;
    lo = lo - (hi - s.x);
    return make_float2(hi, lo);
}

// ---------------------------------------------------------------------------
// Kernel 1: df-precision prefix of omegas -> per-segment fp32 table.
// ---------------------------------------------------------------------------
__global__ void k_base(const float* __restrict__ freq,
                       const float* __restrict__ amp) {
    int seq  = blockIdx.x;
    int i    = threadIdx.x;
    int lane = i & 31;
    int wid  = i >> 5;

    float f = freq[seq * NN + i];
    float a = amp [seq * NN + i];

    float g_hi = f * CF_F;
    float g_lo = fmaf(f, CF_F, -g_hi);      // exact product tail
    float2 x = make_float2(g_hi, g_lo);

    #pragma unroll
    for (int off = 1; off < 32; off <<= 1) {
        float yh = __shfl_up_sync(0xFFFFFFFFu, x.x, off);
        float yl = __shfl_up_sync(0xFFFFFFFFu, x.y, off);
        if (lane >= off) x = df_add(x, make_float2(yh, yl));
    }

    __shared__ float2 wsum[16];
    if (lane == 31) wsum[wid] = x;
    __syncthreads();
    if (wid == 0) {
        float2 y = (lane < 16) ? wsum[lane] : make_float2(0.0f, 0.0f);
        #pragma unroll
        for (int off = 1; off < 16; off <<= 1) {
            float zh = __shfl_up_sync(0xFFFFFFFFu, y.x, off);
            float zl = __shfl_up_sync(0xFFFFFFFFu, y.y, off);
            if (lane >= off) y = df_add(y, make_float2(zh, zl));
        }
        if (lane < 16) wsum[lane] = y;
    }
    __syncthreads();
    float2 Q = x;
    if (wid > 0) Q = df_add(Q, wsum[wid - 1]);

    float2 Q32  = make_float2(32.0f * Q.x, 32.0f * Q.y);
    float2 g16n = make_float2(-16.0f * g_hi, -16.0f * g_lo);
    float2 P = df_add(Q32, g16n);

    float q = floorf(P.x * INV_CMOD_F);
    float m = fmaf(-q, CMOD_F, P.x) + P.y;

    float fnext = (i < NN - 1) ? freq[seq * NN + i + 1] : f;
    float anext = (i < NN - 1) ? amp [seq * NN + i + 1] : a;
    float dg64 = (i < NN - 1) ? (fnext * CF_F - g_hi) * (1.0f / 64.0f) : 0.0f;
    float da   = (i < NN - 1) ? (anext - a) : 0.0f;

    size_t tb = (size_t)seq * NE;
    d_tab[tb + i + 1] = make_float4(m, g_hi, dg64, a);
    d_da [tb + i + 1] = da;
    if (i == 0) {
        d_tab[tb] = make_float4(0.0f, g_hi, 0.0f, a);
        d_da [tb] = 0.0f;
    }
}

// ---------------------------------------------------------------------------
// Kernel 2: synthesis. Block = 256 thr = 8 sine-chunks (warps) x
// [2 segments x 16 lanes]; 2 t-samples per thread per table load.
// Mod by fl32(2*pi) uses the round-to-nearest magic trick: all fma-pipe,
// no CVT in the chain. Phase is provably >= 0 inside every segment
// (concave/convex parabola with phi(0)=0, phi(32)=16(g+g') > 0), so
// phi in [0, ~41) and q in [0, 7) -- the magic fma is exact there.
// Table loads software-pipelined one iteration ahead (arrays padded).
// Fixed-order smem reduction => bitwise deterministic.
// ---------------------------------------------------------------------------
__global__ void __launch_bounds__(256) k_main(float* __restrict__ out) {
    int tid  = threadIdx.x;
    int c    = tid >> 5;            // sine chunk 0..7
    int lane = tid & 31;
    int seg2 = lane >> 4;           // local segment 0..1
    int jg   = lane & 15;           // samples j = jg, jg+16

    int q = blockIdx.x % NQ2;       // segment pair
    int b = blockIdx.x / NQ2;
    int e = 2 * q + seg2;           // extended segment index (may be 513)
    int ec = (e > NE - 1) ? (NE - 1) : e;   // clamp for safe loads

    float u0 = (float)(jg + 1);
    float u1 = u0 + 16.0f;
    float s0 = u0 * u0, s1 = u1 * u1;
    float w0 = (float)(2 * jg + 1) * (1.0f / 64.0f);
    float w1 = w0 + 0.5f;

    size_t rowbase = (size_t)(b * SS + c * S_PER_CHUNK) * NE + ec;
    const float4* tp = d_tab + rowbase;
    const float*  dp = d_da  + rowbase;

    float4 v  = __ldg(tp);
    float  da = __ldg(dp);

    float a0 = 0.0f, a1 = 0.0f;
    #pragma unroll 8
    for (int k = 0; k < S_PER_CHUNK; k++) {
        float4 vn  = __ldg(tp + NE);    // prefetch next sine's entry
        float  dan = __ldg(dp + NE);

        float p0 = fmaf(s0, v.z, fmaf(u0, v.y, v.x));
        float p1 = fmaf(s1, v.z, fmaf(u1, v.y, v.x));

        float q0 = fmaf(p0, INV_CMOD_F, MAGIC_F) - MAGIC_F;  // rn(p/C)
        float q1 = fmaf(p1, INV_CMOD_F, MAGIC_F) - MAGIC_F;

        float r0 = fmaf(q0, -CMOD_F, p0);   // in [-pi, pi]
        float r1 = fmaf(q1, -CMOD_F, p1);

        float m0 = fmaf(w0, da, v.w);
        float m1 = fmaf(w1, da, v.w);

        a0 = fmaf(m0, __sinf(r0), a0);
        a1 = fmaf(m1, __sinf(r1), a1);

        v = vn; da = dan;
        tp += NE; dp += NE;
    }

    __shared__ float sred[NCHUNK][2 * 33];
    int base = seg2 * 33 + jg;
    sred[c][base     ] = a0;
    sred[c][base + 16] = a1;
    __syncthreads();

    if (tid < 64) {
        int e_loc = tid >> 5;           // 0..1
        int j     = tid & 31;
        int e_out = 2 * q + e_loc;
        float s = 0.0f;
        #pragma unroll
        for (int cc = 0; cc < NCHUNK; cc++) s += sred[cc][e_loc * 33 + j];

        bool valid = (e_out <= NE - 1);
        if (e_out == 0 || e_out == NE - 1) valid = valid && (j < 16);
        if (valid) {
            int t = (e_out == 0) ? j : 16 + 32 * (e_out - 1) + j;
            out[b * LL + t] = s;
        }
    }
}

// ---------------------------------------------------------------------------
extern "C" void kernel_launch(void* const* d_in, const int* in_sizes, int n_in,
                              void* d_out, int out_size) {
    const float* freq = (const float*)d_in[0];
    const float* amp  = (const float*)d_in[1];
    float* out = (float*)d_out;

    k_base<<<BB * SS, NN>>>(freq, amp);        // 1024 blocks x 512
    k_main<<<BB * NQ2, 256>>>(out);            // 1028 blocks x 256
}

// round 7
// speedup vs baseline: 1.2388x; 1.1026x over previous
#include <cuda_runtime.h>
#include <math.h>

// Problem constants
#define BB 4
#define SS 256
#define NN 512
#define RR 32
#define LL (NN * RR)          // 16384 output samples per batch
#define NCHUNK 8
#define S_PER_CHUNK (SS / NCHUNK)  // 32
#define NE 513                // extended segments: head(1) + 511 mids + tail
#define NQ2 257               // ceil(513/2) segment-pairs per batch

// Reference-matching constants
#define TWO_PI_D 6.283185307179586
#define CF_F  ((float)(TWO_PI_D / 44100.0))
#define CMOD_F ((float)TWO_PI_D)
#define INV_CMOD_F ((float)(1.0 / (double)((float)TWO_PI_D)))
#define MAGIC_F 12582912.0f   // 1.5*2^23: fma(x,s,MAGIC)-MAGIC = nearbyint(x*s)

// Scratch
__device__ float4 d_tab[BB * SS * NE];       // {base_mod, g, dg/64, a}
__device__ float  d_da [BB * SS * NE];       // a_{i+1}-a_i

// ---------------------------------------------------------------------------
// double-float helpers (all-fp32 compensated arithmetic)
// ---------------------------------------------------------------------------
__device__ __forceinline__ float2 two_sum(float a, float b) {
    float s  = a + b;
    float bb = s - a;
    float e  = (a - (s - bb)) + (b - bb);
    return make_float2(s, e);
}
__device__ __forceinline__ float2 df_add(float2 a, float2 b) {
    float2 s = two_sum(a.x, b.x);
    float lo = s.y + (a.y + b.y);
    float hi = s.x + lo;
    lo = lo - (hi - s.x);
    return make_float2(hi, lo);
}

// ---------------------------------------------------------------------------
// Kernel 1: df-precision prefix of omegas -> per-segment fp32 table.
// ---------------------------------------------------------------------------
__global__ void k_base(const float* __restrict__ freq,
                       const float* __restrict__ amp) {
    int seq  = blockIdx.x;
    int i    = threadIdx.x;
    int lane = i & 31;
    int wid  = i >> 5;

    float f = freq[seq * NN + i];
    float a = amp [seq * NN + i];

    float g_hi = f * CF_F;
    float g_lo = fmaf(f, CF_F, -g_hi);      // exact product tail
    float2 x = make_float2(g_hi, g_lo);

    #pragma unroll
    for (int off = 1; off < 32; off <<= 1) {
        float yh = __shfl_up_sync(0xFFFFFFFFu, x.x, off);
        float yl = __shfl_up_sync(0xFFFFFFFFu, x.y, off);
        if (lane >= off) x = df_add(x, make_float2(yh, yl));
    }

    __shared__ float2 wsum[16];
    if (lane == 31) wsum[wid] = x;
    __syncthreads();
    if (wid == 0) {
        float2 y = (lane < 16) ? wsum[lane] : make_float2(0.0f, 0.0f);
        #pragma unroll
        for (int off = 1; off < 16; off <<= 1) {
            float zh = __shfl_up_sync(0xFFFFFFFFu, y.x, off);
            float zl = __shfl_up_sync(0xFFFFFFFFu, y.y, off);
            if (lane >= off) y = df_add(y, make_float2(zh, zl));
        }
        if (lane < 16) wsum[lane] = y;
    }
    __syncthreads();
    float2 Q = x;
    if (wid > 0) Q = df_add(Q, wsum[wid - 1]);

    float2 Q32  = make_float2(32.0f * Q.x, 32.0f * Q.y);
    float2 g16n = make_float2(-16.0f * g_hi, -16.0f * g_lo);
    float2 P = df_add(Q32, g16n);

    float q = floorf(P.x * INV_CMOD_F);
    float m = fmaf(-q, CMOD_F, P.x) + P.y;

    float fnext = (i < NN - 1) ? freq[seq * NN + i + 1] : f;
    float anext = (i < NN - 1) ? amp [seq * NN + i + 1] : a;
    float dg64 = (i < NN - 1) ? (fnext * CF_F - g_hi) * (1.0f / 64.0f) : 0.0f;
    float da   = (i < NN - 1) ? (anext - a) : 0.0f;

    size_t tb = (size_t)seq * NE;
    d_tab[tb + i + 1] = make_float4(m, g_hi, dg64, a);
    d_da [tb + i + 1] = da;
    if (i == 0) {
        d_tab[tb] = make_float4(0.0f, g_hi, 0.0f, a);
        d_da [tb] = 0.0f;
    }
}

// ---------------------------------------------------------------------------
// Kernel 2: synthesis. Block = 256 thr = 8 sine-chunks (warps) x
// [2 segments x 16 lanes]; 2 t-samples per thread per table load.
// The 32-sine loop is processed in batches of 4: all 8 loads issued
// front-batched (MLP), then 8 independent phase->sin chains.
// __launch_bounds__(256,4) grants a 64-reg budget so ptxas can keep the
// whole batch in registers instead of serializing at 32 regs.
// Fixed-order smem reduction => bitwise deterministic.
// ---------------------------------------------------------------------------
__global__ void __launch_bounds__(256, 4) k_main(float* __restrict__ out) {
    int tid  = threadIdx.x;
    int c    = tid >> 5;            // sine chunk 0..7
    int lane = tid & 31;
    int seg2 = lane >> 4;           // local segment 0..1
    int jg   = lane & 15;           // samples j = jg, jg+16

    int q = blockIdx.x % NQ2;       // segment pair
    int b = blockIdx.x / NQ2;
    int e = 2 * q + seg2;           // extended segment index (may be 513)
    int ec = (e > NE - 1) ? (NE - 1) : e;   // clamp for safe loads

    float u0 = (float)(jg + 1);
    float u1 = u0 + 16.0f;
    float s0 = u0 * u0, s1 = u1 * u1;
    float w0 = (float)(2 * jg + 1) * (1.0f / 64.0f);
    float w1 = w0 + 0.5f;

    size_t rowbase = (size_t)(b * SS + c * S_PER_CHUNK) * NE + ec;
    const float4* tp = d_tab + rowbase;
    const float*  dp = d_da  + rowbase;

    float a0 = 0.0f, a1 = 0.0f;

    #pragma unroll
    for (int k0 = 0; k0 < S_PER_CHUNK; k0 += 4) {
        // batch loads: 8 independent LDGs up front
        float4 v0 = __ldg(tp);
        float4 v1 = __ldg(tp + NE);
        float4 v2 = __ldg(tp + 2 * NE);
        float4 v3 = __ldg(tp + 3 * NE);
        float  d0 = __ldg(dp);
        float  d1 = __ldg(dp + NE);
        float  d2 = __ldg(dp + 2 * NE);
        float  d3 = __ldg(dp + 3 * NE);
        tp += 4 * NE; dp += 4 * NE;

        // 8 independent phase->sin chains
        float p00 = fmaf(s0, v0.z, fmaf(u0, v0.y, v0.x));
        float p01 = fmaf(s1, v0.z, fmaf(u1, v0.y, v0.x));
        float p10 = fmaf(s0, v1.z, fmaf(u0, v1.y, v1.x));
        float p11 = fmaf(s1, v1.z, fmaf(u1, v1.y, v1.x));
        float p20 = fmaf(s0, v2.z, fmaf(u0, v2.y, v2.x));
        float p21 = fmaf(s1, v2.z, fmaf(u1, v2.y, v2.x));
        float p30 = fmaf(s0, v3.z, fmaf(u0, v3.y, v3.x));
        float p31 = fmaf(s1, v3.z, fmaf(u1, v3.y, v3.x));

        float q00 = fmaf(p00, INV_CMOD_F, MAGIC_F) - MAGIC_F;
        float q01 = fmaf(p01, INV_CMOD_F, MAGIC_F) - MAGIC_F;
        float q10 = fmaf(p10, INV_CMOD_F, MAGIC_F) - MAGIC_F;
        float q11 = fmaf(p11, INV_CMOD_F, MAGIC_F) - MAGIC_F;
        float q20 = fmaf(p20, INV_CMOD_F, MAGIC_F) - MAGIC_F;
        float q21 = fmaf(p21, INV_CMOD_F, MAGIC_F) - MAGIC_F;
        float q30 = fmaf(p30, INV_CMOD_F, MAGIC_F) - MAGIC_F;
        float q31 = fmaf(p31, INV_CMOD_F, MAGIC_F) - MAGIC_F;

        float r00 = fmaf(q00, -CMOD_F, p00);
        float r01 = fmaf(q01, -CMOD_F, p01);
        float r10 = fmaf(q10, -CMOD_F, p10);
        float r11 = fmaf(q11, -CMOD_F, p11);
        float r20 = fmaf(q20, -CMOD_F, p20);
        float r21 = fmaf(q21, -CMOD_F, p21);
        float r30 = fmaf(q30, -CMOD_F, p30);
        float r31 = fmaf(q31, -CMOD_F, p31);

        float m00 = fmaf(w0, d0, v0.w);
        float m01 = fmaf(w1, d0, v0.w);
        float m10 = fmaf(w0, d1, v1.w);
        float m11 = fmaf(w1, d1, v1.w);
        float m20 = fmaf(w0, d2, v2.w);
        float m21 = fmaf(w1, d2, v2.w);
        float m30 = fmaf(w0, d3, v3.w);
        float m31 = fmaf(w1, d3, v3.w);

        a0 = fmaf(m00, __sinf(r00), a0);
        a1 = fmaf(m01, __sinf(r01), a1);
        a0 = fmaf(m10, __sinf(r10), a0);
        a1 = fmaf(m11, __sinf(r11), a1);
        a0 = fmaf(m20, __sinf(r20), a0);
        a1 = fmaf(m21, __sinf(r21), a1);
        a0 = fmaf(m30, __sinf(r30), a0);
        a1 = fmaf(m31, __sinf(r31), a1);
    }

    __shared__ float sred[NCHUNK][2 * 33];
    int base = seg2 * 33 + jg;
    sred[c][base     ] = a0;
    sred[c][base + 16] = a1;
    __syncthreads();

    if (tid < 64) {
        int e_loc = tid >> 5;           // 0..1
        int j     = tid & 31;
        int e_out = 2 * q + e_loc;
        float s = 0.0f;
        #pragma unroll
        for (int cc = 0; cc < NCHUNK; cc++) s += sred[cc][e_loc * 33 + j];

        bool valid = (e_out <= NE - 1);
        if (e_out == 0 || e_out == NE - 1) valid = valid && (j < 16);
        if (valid) {
            int t = (e_out == 0) ? j : 16 + 32 * (e_out - 1) + j;
            out[b * LL + t] = s;
        }
    }
}

// ---------------------------------------------------------------------------
extern "C" void kernel_launch(void* const* d_in, const int* in_sizes, int n_in,
                              void* d_out, int out_size) {
    const float* freq = (const float*)d_in[0];
    const float* amp  = (const float*)d_in[1];
    float* out = (float*)d_out;

    k_base<<<BB * SS, NN>>>(freq, amp);        // 1024 blocks x 512
    k_main<<<BB * NQ2, 256>>>(out);            // 1028 blocks x 256
}